// round 6
// baseline (speedup 1.0000x reference)
#include <cuda_runtime.h>

// SparseTopKLayer: out = x + ((x*rms)*w)*mask*gamma   (per row)
// Rank on |x*w| (rms>0 row-constant -> identical ordering).
// TWO rows per CTA, 256 threads, 8 elems/thread/row in registers:
// w,g loaded once per 2 rows; barriers/scans shared; warp0 scans row0
// while warp1 scans row1. Exact threshold via Gaussian-quantile window +
// adaptive histogram select (exact for arbitrary data via re-windowing).

constexpr int D    = 2048;
constexpr int T    = 256;
constexpr int BINS = 128;

__device__ __forceinline__ float inv_phi_tail(float q) {
    // Phi^{-1}(1-q), q in (0,0.5]; Abramowitz-Stegun 26.2.23, |err|<4.5e-4
    q = fminf(fmaxf(q, 1e-7f), 0.4999f);
    float s = sqrtf(-2.0f * __logf(q));
    return s - (2.30753f + 0.27061f * s) / (1.0f + s * (0.99229f + 0.04481f * s));
}

// warp0/warp1: suffix-scan hist, classify, publish new window/mode.
__device__ __forceinline__ void scan_publish(
    const unsigned* __restrict__ h, int rnd, int lane,
    volatile unsigned* lo_sh, volatile unsigned* hi_sh, volatile unsigned* thr_sh,
    volatile int* r_sh, volatile int* mode_sh, const volatile unsigned* above_sh)
{
    const unsigned lo = *lo_sh, hi = *hi_sh;
    const unsigned range = hi - lo;
    const int s = (range > (unsigned)BINS) ? (25 - __clz(range - 1u)) : 0;

    uint4 hv = *reinterpret_cast<const uint4*>(&h[lane * 4]);
    unsigned hr[4] = {hv.x, hv.y, hv.z, hv.w};
    unsigned bs = hr[0] + hr[1] + hr[2] + hr[3];
    unsigned S = bs;
    #pragma unroll
    for (int o = 1; o < 32; o <<= 1) {
        unsigned v = __shfl_down_sync(0xffffffffu, S, o);
        if (lane + o < 32) S += v;
    }
    unsigned total = __shfl_sync(0xffffffffu, S, 0);
    int r = *r_sh;
    unsigned above = *above_sh;
    if (rnd == 0) r -= (int)above;

    if (r <= 0) {                       // threshold above window
        if (lane == 0) { *lo_sh = hi; *hi_sh = 0x80000000u;
                         *r_sh = r + (int)above; *mode_sh = 0; }
    } else if ((unsigned)r > total) {   // threshold below window
        if (lane == 0) { *hi_sh = lo; *lo_sh = 0u;
                         *r_sh = r - (int)total; *mode_sh = 0; }
    } else {
        unsigned suf = S - bs;          // count in strictly-higher lanes
        int bj = -1; unsigned cnt = 0, abv = 0;
        #pragma unroll
        for (int j = 3; j >= 0; j--) {
            unsigned ns = suf + hr[j];
            if (suf < (unsigned)r && ns >= (unsigned)r) { bj = j; cnt = hr[j]; abv = suf; }
            suf = ns;
        }
        unsigned bal = __ballot_sync(0xffffffffu, bj >= 0);
        int src = __ffs(bal) - 1;
        unsigned B = __shfl_sync(0xffffffffu, (unsigned)(lane * 4 + bj), src);
        cnt = __shfl_sync(0xffffffffu, cnt, src);
        abv = __shfl_sync(0xffffffffu, abv, src);
        if (lane == 0) {
            int r2 = r - (int)abv;
            unsigned nlo = lo + (B << s);
            unsigned nhi = lo + ((B + 1u) << s);
            if (nhi > hi) nhi = hi;
            *lo_sh = nlo; *hi_sh = nhi; *r_sh = r2;
            if (s == 0)              { *mode_sh = 1; *thr_sh = nlo; }
            else if ((int)cnt == r2) { *mode_sh = 2; }   // thr = min in bucket
            else if (r2 == 1)        { *mode_sh = 3; }   // thr = max in bucket
            else                     { *mode_sh = 0; }
        }
    }
}

__global__ void __launch_bounds__(T, 4) sparse_topk_kernel(
    const float* __restrict__ x,
    const float* __restrict__ w,
    const float* __restrict__ g,
    const int* __restrict__ kptr,
    float* __restrict__ out)
{
    const int t    = threadIdx.x;
    const int lane = t & 31;
    const int wid  = t >> 5;
    const size_t base = (size_t)blockIdx.x * 2 * (D / 4);

    __shared__ float4   red[8];
    __shared__ __align__(16) unsigned hist[2][2][BINS];   // [row][buf]
    __shared__ unsigned lo_sh[2], hi_sh[2], thr_sh[2], thrmin_sh[2], thrmax_sh[2], above_sh[2];
    __shared__ int      r_sh[2], mode_sh[2];
    __shared__ float    rms_sh[2];

    // ---- loads: two rows of x, one w ----
    const float4* xr0 = reinterpret_cast<const float4*>(x) + base;
    const float4* xr1 = xr0 + (D / 4);
    const float4* wv  = reinterpret_cast<const float4*>(w);
    float4 a0 = xr0[t], b0 = xr0[t + T];
    float4 a1 = xr1[t], b1 = xr1[t + T];
    float4 wa = wv[t],  wb = wv[t + T];

    float xv0[8] = {a0.x,a0.y,a0.z,a0.w,b0.x,b0.y,b0.z,b0.w};
    float xv1[8] = {a1.x,a1.y,a1.z,a1.w,b1.x,b1.y,b1.z,b1.w};
    float xw0[8], xw1[8];
    float ss0 = 0.f, sw0 = 0.f, ss1 = 0.f, sw1 = 0.f;
    {
        float wf[8] = {wa.x,wa.y,wa.z,wa.w,wb.x,wb.y,wb.z,wb.w};
        #pragma unroll
        for (int i = 0; i < 8; i++) {
            xw0[i] = xv0[i] * wf[i];
            xw1[i] = xv1[i] * wf[i];
            ss0 = fmaf(xv0[i], xv0[i], ss0);
            sw0 = fmaf(xw0[i], xw0[i], sw0);
            ss1 = fmaf(xv1[i], xv1[i], ss1);
            sw1 = fmaf(xw1[i], xw1[i], sw1);
        }
    }
    #pragma unroll
    for (int o = 16; o > 0; o >>= 1) {
        ss0 += __shfl_xor_sync(0xffffffffu, ss0, o);
        sw0 += __shfl_xor_sync(0xffffffffu, sw0, o);
        ss1 += __shfl_xor_sync(0xffffffffu, ss1, o);
        sw1 += __shfl_xor_sync(0xffffffffu, sw1, o);
    }
    if (lane == 0) red[wid] = make_float4(ss0, sw0, ss1, sw1);
    if (t < 128) reinterpret_cast<uint4*>(hist)[t] = make_uint4(0u,0u,0u,0u);
    if (t < 2) { above_sh[t] = 0u; thrmin_sh[t] = 0xFFFFFFFFu; thrmax_sh[t] = 0u; }
    __syncthreads();

    // ---- warp0: rms + Gaussian windows for both rows ----
    if (t < 8) {
        float4 v = red[t];
        #pragma unroll
        for (int o = 4; o > 0; o >>= 1) {
            v.x += __shfl_xor_sync(0xffu, v.x, o);
            v.y += __shfl_xor_sync(0xffu, v.y, o);
            v.z += __shfl_xor_sync(0xffu, v.z, o);
            v.w += __shfl_xor_sync(0xffu, v.w, o);
        }
        if (t == 0) {
            int k = *kptr;
            float t1 = inv_phi_tail((float)(k + 64) * (0.5f / (float)D));
            float t2 = inv_phi_tail((float)(k - 64 > 1 ? k - 64 : 1) * (0.5f / (float)D));
            rms_sh[0] = rsqrtf(v.x * (1.0f/(float)D) + 1e-6f);
            rms_sh[1] = rsqrtf(v.z * (1.0f/(float)D) + 1e-6f);
            float sg0 = sqrtf(v.y * (1.0f/(float)D));
            float sg1 = sqrtf(v.w * (1.0f/(float)D));
            unsigned l0 = (t1 > 0.f) ? __float_as_uint(t1 * sg0) : 0u;
            unsigned h0 = __float_as_uint(fmaxf(t2, 0.f) * sg0);
            if (h0 <= l0) h0 = l0 + 1u;
            unsigned l1 = (t1 > 0.f) ? __float_as_uint(t1 * sg1) : 0u;
            unsigned h1 = __float_as_uint(fmaxf(t2, 0.f) * sg1);
            if (h1 <= l1) h1 = l1 + 1u;
            lo_sh[0] = l0; hi_sh[0] = h0; r_sh[0] = k; mode_sh[0] = 0;
            lo_sh[1] = l1; hi_sh[1] = h1; r_sh[1] = k; mode_sh[1] = 0;
        }
    }
    __syncthreads();

    // ---- shared adaptive select loop for both rows ----
    unsigned thr0 = 0u, thr1 = 0u;
    bool done0 = false, done1 = false;
    int p0 = 0, p1 = 0, rnd0 = 0, rnd1 = 0;

    while (!done0 || !done1) {
        // Phase A: histograms (+ round-0 above counts), zero next buffers
        unsigned lo0 = lo_sh[0], hi0 = hi_sh[0], lo1 = lo_sh[1], hi1 = hi_sh[1];
        unsigned rg0 = hi0 - lo0, rg1 = hi1 - lo1;
        int s0 = (rg0 > (unsigned)BINS) ? (25 - __clz(rg0 - 1u)) : 0;
        int s1 = (rg1 > (unsigned)BINS) ? (25 - __clz(rg1 - 1u)) : 0;
        unsigned ab0 = 0u, ab1 = 0u;
        #pragma unroll
        for (int i = 0; i < 8; i++) {
            if (!done0) {
                unsigned ub = __float_as_uint(fabsf(xw0[i]));
                unsigned d = ub - lo0;
                if (d < rg0) atomicAdd(&hist[0][p0][d >> s0], 1u);
                if (rnd0 == 0) ab0 += (ub >= hi0);
            }
            if (!done1) {
                unsigned ub = __float_as_uint(fabsf(xw1[i]));
                unsigned d = ub - lo1;
                if (d < rg1) atomicAdd(&hist[1][p1][d >> s1], 1u);
                if (rnd1 == 0) ab1 += (ub >= hi1);
            }
        }
        if (!done0 && rnd0 == 0) {
            ab0 = __reduce_add_sync(0xffffffffu, ab0);
            if (lane == 0) atomicAdd(&above_sh[0], ab0);
        }
        if (!done1 && rnd1 == 0) {
            ab1 = __reduce_add_sync(0xffffffffu, ab1);
            if (lane == 0) atomicAdd(&above_sh[1], ab1);
        }
        if (t < BINS) {
            if (!done0) hist[0][p0 ^ 1][t] = 0u;
            if (!done1) hist[1][p1 ^ 1][t] = 0u;
        }
        __syncthreads();

        // Phase B: parallel scans
        if (wid == 0 && !done0)
            scan_publish(hist[0][p0], rnd0, lane, &lo_sh[0], &hi_sh[0], &thr_sh[0],
                         &r_sh[0], &mode_sh[0], &above_sh[0]);
        if (wid == 1 && !done1)
            scan_publish(hist[1][p1], rnd1, lane, &lo_sh[1], &hi_sh[1], &thr_sh[1],
                         &r_sh[1], &mode_sh[1], &above_sh[1]);
        __syncthreads();

        // Phase C: min/max reductions for rows that hit an exit bucket
        int m0 = done0 ? 1 : mode_sh[0];
        int m1 = done1 ? 1 : mode_sh[1];
        if (!done0 && m0 >= 2) {
            unsigned nlo = lo_sh[0], nr = hi_sh[0] - nlo;
            if (m0 == 2) {
                unsigned lm = 0xFFFFFFFFu;
                #pragma unroll
                for (int i = 0; i < 8; i++) {
                    unsigned ub = __float_as_uint(fabsf(xw0[i]));
                    if (ub - nlo < nr) lm = min(lm, ub);
                }
                lm = __reduce_min_sync(0xffffffffu, lm);
                if (lane == 0) atomicMin(&thrmin_sh[0], lm);
            } else {
                unsigned lm = 0u;
                #pragma unroll
                for (int i = 0; i < 8; i++) {
                    unsigned ub = __float_as_uint(fabsf(xw0[i]));
                    if (ub - nlo < nr) lm = max(lm, ub);
                }
                lm = __reduce_max_sync(0xffffffffu, lm);
                if (lane == 0) atomicMax(&thrmax_sh[0], lm);
            }
        }
        if (!done1 && m1 >= 2) {
            unsigned nlo = lo_sh[1], nr = hi_sh[1] - nlo;
            if (m1 == 2) {
                unsigned lm = 0xFFFFFFFFu;
                #pragma unroll
                for (int i = 0; i < 8; i++) {
                    unsigned ub = __float_as_uint(fabsf(xw1[i]));
                    if (ub - nlo < nr) lm = min(lm, ub);
                }
                lm = __reduce_min_sync(0xffffffffu, lm);
                if (lane == 0) atomicMin(&thrmin_sh[1], lm);
            } else {
                unsigned lm = 0u;
                #pragma unroll
                for (int i = 0; i < 8; i++) {
                    unsigned ub = __float_as_uint(fabsf(xw1[i]));
                    if (ub - nlo < nr) lm = max(lm, ub);
                }
                lm = __reduce_max_sync(0xffffffffu, lm);
                if (lane == 0) atomicMax(&thrmax_sh[1], lm);
            }
        }
        __syncthreads();

        if (!done0) {
            if      (m0 == 1) { thr0 = thr_sh[0];    done0 = true; }
            else if (m0 == 2) { thr0 = thrmin_sh[0]; done0 = true; }
            else if (m0 == 3) { thr0 = thrmax_sh[0]; done0 = true; }
            else              { p0 ^= 1; rnd0++; }
        }
        if (!done1) {
            if      (m1 == 1) { thr1 = thr_sh[1];    done1 = true; }
            else if (m1 == 2) { thr1 = thrmin_sh[1]; done1 = true; }
            else if (m1 == 3) { thr1 = thrmax_sh[1]; done1 = true; }
            else              { p1 ^= 1; rnd1++; }
        }
    }

    // ---- epilogue: both rows ----
    const float4* gv = reinterpret_cast<const float4*>(g);
    float4 ga = gv[t], gb = gv[t + T];
    float gf[8] = {ga.x,ga.y,ga.z,ga.w,gb.x,gb.y,gb.z,gb.w};
    const float rms0 = rms_sh[0], rms1 = rms_sh[1];
    const float tf0 = __uint_as_float(thr0), tf1 = __uint_as_float(thr1);

    float fo0[8], fo1[8];
    #pragma unroll
    for (int i = 0; i < 8; i++) {
        float rg0 = rms0 * gf[i];
        float rg1 = rms1 * gf[i];
        fo0[i] = xv0[i] + ((fabsf(xw0[i]) >= tf0) ? xw0[i] * rg0 : 0.0f);
        fo1[i] = xv1[i] + ((fabsf(xw1[i]) >= tf1) ? xw1[i] * rg1 : 0.0f);
    }
    float4* o0 = reinterpret_cast<float4*>(out) + base;
    float4* o1 = o0 + (D / 4);
    o0[t]     = make_float4(fo0[0], fo0[1], fo0[2], fo0[3]);
    o0[t + T] = make_float4(fo0[4], fo0[5], fo0[6], fo0[7]);
    o1[t]     = make_float4(fo1[0], fo1[1], fo1[2], fo1[3]);
    o1[t + T] = make_float4(fo1[4], fo1[5], fo1[6], fo1[7]);
}

extern "C" void kernel_launch(void* const* d_in, const int* in_sizes, int n_in,
                              void* d_out, int out_size)
{
    const float* x = (const float*)d_in[0];
    const float* w = (const float*)d_in[1];
    const float* g = (const float*)d_in[2];
    const int*   k = (const int*)d_in[3];

    int N = in_sizes[0] / D;   // 32768 rows
    sparse_topk_kernel<<<N / 2, T>>>(x, w, g, k, (float*)d_out);
}

// round 7
// speedup vs baseline: 1.0143x; 1.0143x over previous
#include <cuda_runtime.h>

// SparseTopKLayer: out = x + ((x*rms)*w)*mask*gamma
//   rms = rsqrt(mean(x^2)+1e-6); mask = |x_norm| >= kth_largest(|x_norm|, k)
// Rank on |x*w| (rms>0 row-constant -> identical ordering).
// One CTA per row, 256 threads, 8 elems/thread.
// Gaussian-quantile window; adaptive histogram select with FUSED per-bin
// min/max value tracking, so warp0 resolves the exact threshold with no
// extra block-wide pass. Exact for arbitrary data via re-windowing.

constexpr int D    = 2048;
constexpr int T    = 256;
constexpr int BINS = 128;

__device__ __forceinline__ float inv_phi_tail(float q) {
    // Phi^{-1}(1-q), q in (0,0.5]; Abramowitz-Stegun 26.2.23, |err|<4.5e-4
    q = fminf(fmaxf(q, 1e-7f), 0.4999f);
    float s = sqrtf(-2.0f * __logf(q));
    return s - (2.30753f + 0.27061f * s) / (1.0f + s * (0.99229f + 0.04481f * s));
}

__global__ void __launch_bounds__(T, 7) sparse_topk_kernel(
    const float* __restrict__ x,
    const float* __restrict__ w,
    const float* __restrict__ g,
    const int* __restrict__ kptr,
    float* __restrict__ out)
{
    const int row  = blockIdx.x;
    const int t    = threadIdx.x;
    const int lane = t & 31;
    const int wid  = t >> 5;

    __shared__ float2   red[8];
    __shared__ __align__(16) unsigned cnt[2][BINS];
    __shared__ unsigned mnv[2][BINS], mxv[2][BINS];
    __shared__ unsigned lo_sh, hi_sh, thr_sh, above_sh;
    __shared__ int      r_sh, mode_sh;
    __shared__ float    rms_sh;

    // ---- load x,w; keep only xw in regs; dual sums ----
    const float4* xr = reinterpret_cast<const float4*>(x) + (size_t)row * (D / 4);
    const float4* wv = reinterpret_cast<const float4*>(w);
    float xw[8];
    float ss = 0.0f, sw = 0.0f;
    {
        float4 xa = xr[t], xb = xr[t + T];
        float4 wa = wv[t], wb = wv[t + T];
        float xv[8] = {xa.x,xa.y,xa.z,xa.w,xb.x,xb.y,xb.z,xb.w};
        float wf[8] = {wa.x,wa.y,wa.z,wa.w,wb.x,wb.y,wb.z,wb.w};
        #pragma unroll
        for (int i = 0; i < 8; i++) {
            xw[i] = xv[i] * wf[i];
            ss = fmaf(xv[i], xv[i], ss);
            sw = fmaf(xw[i], xw[i], sw);
        }
    }
    #pragma unroll
    for (int o = 16; o > 0; o >>= 1) {
        ss += __shfl_xor_sync(0xffffffffu, ss, o);
        sw += __shfl_xor_sync(0xffffffffu, sw, o);
    }
    if (lane == 0) red[wid] = make_float2(ss, sw);
    if (t < BINS) {
        cnt[0][t] = 0u;           cnt[1][t] = 0u;
        mnv[0][t] = 0xFFFFFFFFu;  mnv[1][t] = 0xFFFFFFFFu;
        mxv[0][t] = 0u;           mxv[1][t] = 0u;
    }
    if (t == 0) above_sh = 0u;
    __syncthreads();

    // ---- warp0: rms + Gaussian-quantile window ----
    if (t < 8) {
        float2 v = red[t];
        #pragma unroll
        for (int o = 4; o > 0; o >>= 1) {
            v.x += __shfl_xor_sync(0xffu, v.x, o);
            v.y += __shfl_xor_sync(0xffu, v.y, o);
        }
        if (t == 0) {
            rms_sh = rsqrtf(v.x * (1.0f / (float)D) + 1e-6f);
            float sigma = sqrtf(v.y * (1.0f / (float)D));
            int k = *kptr;
            float t1 = inv_phi_tail((float)(k + 64) * (0.5f / (float)D));
            float t2 = inv_phi_tail((float)(k - 64 > 1 ? k - 64 : 1) * (0.5f / (float)D));
            unsigned b1 = (t1 > 0.0f) ? __float_as_uint(t1 * sigma) : 0u;
            unsigned b2 = __float_as_uint(fmaxf(t2, 0.0f) * sigma);
            if (b2 <= b1) b2 = b1 + 1u;
            lo_sh = b1; hi_sh = b2; r_sh = k; mode_sh = 0;
        }
    }
    __syncthreads();

    // ---- adaptive-window select, exits fused into histogram ----
    unsigned thr = 0u;
    int p = 0, rnd = 0;
    while (true) {
        const unsigned lo = lo_sh, hi = hi_sh;
        const unsigned range = hi - lo;
        const int s = (range > (unsigned)BINS) ? (25 - __clz(range - 1u)) : 0;
        unsigned above = 0u;
        #pragma unroll
        for (int i = 0; i < 8; i++) {
            unsigned ub = __float_as_uint(fabsf(xw[i]));
            unsigned d = ub - lo;
            if (d < range) {
                unsigned b = d >> s;
                atomicAdd(&cnt[p][b], 1u);
                atomicMin(&mnv[p][b], ub);
                atomicMax(&mxv[p][b], ub);
            }
            if (rnd == 0) above += (ub >= hi);
        }
        if (rnd == 0) {
            above = __reduce_add_sync(0xffffffffu, above);
            if (lane == 0) atomicAdd(&above_sh, above);
        }
        if (t < BINS) {   // prep buffers for a possible next round
            cnt[p ^ 1][t] = 0u;
            mnv[p ^ 1][t] = 0xFFFFFFFFu;
            mxv[p ^ 1][t] = 0u;
        }
        __syncthreads();

        if (t < 32) {   // warp0: suffix scan + full resolve
            uint4 hv = *reinterpret_cast<const uint4*>(&cnt[p][lane * 4]);
            unsigned hr[4] = {hv.x, hv.y, hv.z, hv.w};
            unsigned bs = hr[0] + hr[1] + hr[2] + hr[3];
            unsigned S = bs;
            #pragma unroll
            for (int o = 1; o < 32; o <<= 1) {
                unsigned v = __shfl_down_sync(0xffffffffu, S, o);
                if (lane + o < 32) S += v;
            }
            unsigned total = __shfl_sync(0xffffffffu, S, 0);
            int r = r_sh;
            if (rnd == 0) r -= (int)above_sh;

            if (r <= 0) {                       // threshold above window
                if (lane == 0) { lo_sh = hi; hi_sh = 0x80000000u;
                                 r_sh = r + (int)above_sh; mode_sh = 0; }
            } else if ((unsigned)r > total) {   // threshold below window
                if (lane == 0) { hi_sh = lo; lo_sh = 0u;
                                 r_sh = r - (int)total; mode_sh = 0; }
            } else {
                unsigned suf = S - bs;          // count in strictly-higher lanes
                int bj = -1; unsigned cb = 0, abv = 0;
                #pragma unroll
                for (int j = 3; j >= 0; j--) {
                    unsigned ns = suf + hr[j];
                    if (suf < (unsigned)r && ns >= (unsigned)r) { bj = j; cb = hr[j]; abv = suf; }
                    suf = ns;
                }
                unsigned bal = __ballot_sync(0xffffffffu, bj >= 0);
                int src = __ffs(bal) - 1;
                unsigned B = __shfl_sync(0xffffffffu, (unsigned)(lane * 4 + bj), src);
                cb  = __shfl_sync(0xffffffffu, cb, src);
                abv = __shfl_sync(0xffffffffu, abv, src);
                if (lane == 0) {
                    int r2 = r - (int)abv;
                    unsigned nlo = lo + (B << s);
                    unsigned nhi = lo + ((B + 1u) << s);
                    if (nhi > hi) nhi = hi;
                    if (s == 0)             { mode_sh = 1; thr_sh = nlo; }
                    else if ((int)cb == r2) { mode_sh = 1; thr_sh = mnv[p][B]; }
                    else if (r2 == 1)       { mode_sh = 1; thr_sh = mxv[p][B]; }
                    else { lo_sh = nlo; hi_sh = nhi; r_sh = r2; mode_sh = 0; }
                }
            }
        }
        __syncthreads();

        if (mode_sh == 1) { thr = thr_sh; break; }
        p ^= 1; rnd++;
    }

    // ---- epilogue: re-load x (L1 hit), load g, write out ----
    const float4* gv = reinterpret_cast<const float4*>(g);
    float4 xa = xr[t], xb = xr[t + T];
    float4 ga = gv[t], gb = gv[t + T];
    float xv[8] = {xa.x,xa.y,xa.z,xa.w,xb.x,xb.y,xb.z,xb.w};
    float gf[8] = {ga.x,ga.y,ga.z,ga.w,gb.x,gb.y,gb.z,gb.w};
    const float rms  = rms_sh;
    const float thrf = __uint_as_float(thr);

    float fo[8];
    #pragma unroll
    for (int i = 0; i < 8; i++) {
        float keep = (fabsf(xw[i]) >= thrf) ? (rms * gf[i]) : 0.0f;
        fo[i] = fmaf(xw[i], keep, xv[i]);
    }
    float4* orow = reinterpret_cast<float4*>(out) + (size_t)row * (D / 4);
    orow[t]     = make_float4(fo[0], fo[1], fo[2], fo[3]);
    orow[t + T] = make_float4(fo[4], fo[5], fo[6], fo[7]);
}

extern "C" void kernel_launch(void* const* d_in, const int* in_sizes, int n_in,
                              void* d_out, int out_size)
{
    const float* x = (const float*)d_in[0];
    const float* w = (const float*)d_in[1];
    const float* g = (const float*)d_in[2];
    const int*   k = (const int*)d_in[3];

    int N = in_sizes[0] / D;   // 32768 rows
    sparse_topk_kernel<<<N, T>>>(x, w, g, k, (float*)d_out);
}